// round 13
// baseline (speedup 1.0000x reference)
#include <cuda_runtime.h>
#include <cstdint>

// ============================================================================
// Monte-Carlo E[softmax(mean + eps)], JAX threefry-partitionable bit-exact RNG.
// R13 (base = R12 packed-FFMA2): slot micro-cuts —
//   * uniform u from ONE I2F of the full 32-bit word (drops both umulhis;
//     rounds vs truncates: <=2^-24 perturbation, mean-neutral);
//   * pairwise (tree) part accumulation — FP dep chain 32 -> 12 cyc;
//   * sample loop unrolled x2 (halved loop/key-index overhead).
// ============================================================================

#define NROWS 16384
#define NCOLS 512
#define WARPS_PER_BLOCK 8
#define NTHREADS (WARPS_PER_BLOCK * 32)
#define KPL 16
#define MAX_SAMPLES 512

typedef unsigned long long u64;

// ---- packed f32x2 helpers ----
__device__ __forceinline__ u64 pack2(float lo, float hi) {
    u64 r;
    asm("mov.b64 %0, {%1, %2};" : "=l"(r) : "f"(lo), "f"(hi));
    return r;
}
__device__ __forceinline__ void unpack2(u64 v, float& lo, float& hi) {
    asm("mov.b64 {%0, %1}, %2;" : "=f"(lo), "=f"(hi) : "l"(v));
}
__device__ __forceinline__ u64 fma2(u64 a, u64 b, u64 c) {
    u64 r;
    asm("fma.rn.f32x2 %0, %1, %2, %3;" : "=l"(r) : "l"(a), "l"(b), "l"(c));
    return r;
}
__device__ __forceinline__ u64 mul2(u64 a, u64 b) {
    u64 r;
    asm("mul.rn.f32x2 %0, %1, %2;" : "=l"(r) : "l"(a), "l"(b));
    return r;
}
__device__ __forceinline__ u64 add2(u64 a, u64 b) {
    u64 r;
    asm("add.rn.f32x2 %0, %1, %2;" : "=l"(r) : "l"(a), "l"(b));
    return r;
}

// a + b on the integer-MAD pipe: a*one + b, `one` opaque to ptxas.
__device__ __forceinline__ uint32_t madd(uint32_t a, uint32_t b, uint32_t one) {
    uint32_t t;
    asm("mad.lo.u32 %0, %1, %2, %3;" : "=r"(t) : "r"(a), "r"(one), "r"(b));
    return t;
}
__device__ __forceinline__ uint32_t rots(uint32_t x1, int r, uint32_t x0) {
    return __funnelshift_l(x1, x1, r) ^ x0;
}

// Compile-time threefry for per-sample subkeys (amortized, per block).
__device__ __forceinline__ void tf_round_c(uint32_t& x0, uint32_t& x1, int r) {
    x0 += x1;
    x1 = __funnelshift_l(x1, x1, r);
    x1 ^= x0;
}
__device__ __forceinline__ uint2 threefry2x32_c(uint32_t k0, uint32_t k1,
                                                uint32_t c0, uint32_t c1) {
    uint32_t k2 = k0 ^ k1 ^ 0x1BD11BDAu;
    uint32_t x0 = c0 + k0;
    uint32_t x1 = c1 + k1;
    tf_round_c(x0,x1,13); tf_round_c(x0,x1,15); tf_round_c(x0,x1,26); tf_round_c(x0,x1,6);
    x0 += k1; x1 += k2 + 1u;
    tf_round_c(x0,x1,17); tf_round_c(x0,x1,29); tf_round_c(x0,x1,16); tf_round_c(x0,x1,24);
    x0 += k2; x1 += k0 + 2u;
    tf_round_c(x0,x1,13); tf_round_c(x0,x1,15); tf_round_c(x0,x1,26); tf_round_c(x0,x1,6);
    x0 += k0; x1 += k1 + 3u;
    tf_round_c(x0,x1,17); tf_round_c(x0,x1,29); tf_round_c(x0,x1,16); tf_round_c(x0,x1,24);
    x0 += k1; x1 += k2 + 4u;
    tf_round_c(x0,x1,13); tf_round_c(x0,x1,15); tf_round_c(x0,x1,26); tf_round_c(x0,x1,6);
    x0 += k2; x1 += k0 + 5u;
    return make_uint2(x0, x1);
}

// Hot fold (R6 form): counter (0, c1), x1 pre-added (c1 + k1). Returns x0^x1.
__device__ __forceinline__ uint32_t tf_fold(
    uint32_t k0, uint32_t k1, uint32_t k2,
    uint32_t i1, uint32_t i2, uint32_t i3, uint32_t i4, uint32_t i5,
    uint32_t x1, uint32_t one)
{
    uint32_t x0;
    x0 = madd(x1, k0, one);          x1 = rots(x1, 13, x0);
    x0 = madd(x1, x0, one);          x1 = rots(x1, 15, x0);
    x0 = madd(x1, x0, one);          x1 = rots(x1, 26, x0);
    x0 = madd(x1, x0, one);          x1 = rots(x1,  6, x0);
    x1 = madd(i1, x1, one);
    x0 = x0 + k1 + x1;               x1 = rots(x1, 17, x0);
    x0 = madd(x1, x0, one);          x1 = rots(x1, 29, x0);
    x0 = madd(x1, x0, one);          x1 = rots(x1, 16, x0);
    x0 = madd(x1, x0, one);          x1 = rots(x1, 24, x0);
    x1 = madd(i2, x1, one);
    x0 = x0 + k2 + x1;               x1 = rots(x1, 13, x0);
    x0 = madd(x1, x0, one);          x1 = rots(x1, 15, x0);
    x0 = madd(x1, x0, one);          x1 = rots(x1, 26, x0);
    x0 = madd(x1, x0, one);          x1 = rots(x1,  6, x0);
    x1 = madd(i3, x1, one);
    x0 = x0 + k0 + x1;               x1 = rots(x1, 17, x0);
    x0 = madd(x1, x0, one);          x1 = rots(x1, 29, x0);
    x0 = madd(x1, x0, one);          x1 = rots(x1, 16, x0);
    x0 = madd(x1, x0, one);          x1 = rots(x1, 24, x0);
    x1 = madd(i4, x1, one);
    x0 = x0 + k1 + x1;               x1 = rots(x1, 13, x0);
    x0 = madd(x1, x0, one);          x1 = rots(x1, 15, x0);
    x0 = madd(x1, x0, one);          x1 = rots(x1, 26, x0);
    x0 = madd(x1, x0, one);          x1 = rots(x1,  6, x0);
    return (x0 + k2) ^ madd(i5, x1, one);
}

// Scalar XLA ErfInv p (rare tail patch-up; P ~ 0.34% per half).
__device__ __noinline__ float erfinv_tail_p(float lg) {
    float w = lg * -0.6931471805599453f;
    float sw;
    asm("sqrt.approx.f32 %0, %1;" : "=f"(sw) : "f"(w));
    float v = sw - 3.0f;
    float p = -0.000200214257f;
    p = fmaf(p, v, 0.000100950558f);
    p = fmaf(p, v, 0.00134934322f);
    p = fmaf(p, v, -0.00367342844f);
    p = fmaf(p, v, 0.00573950773f);
    p = fmaf(p, v, -0.0076224613f);
    p = fmaf(p, v, 0.00943887047f);
    p = fmaf(p, v, 1.00167406f);
    p = fmaf(p, v, 2.83297682f);
    return p;
}

struct KS { uint4 A, B; };

// One sample's packed eval: fills e2[], returns row part-sum (lane-local).
// Packed constants passed by reference struct to keep regs shared.
struct PK {
    u64 SCL, CLO, CM1, C1, CNL2, CN25, P6, P5, P4, P3, P2c, P1, P0;
    float TH;
};

__device__ __forceinline__ float sample_eval(
    const uint4 A, const uint4 B, uint32_t cb, uint32_t one,
    const PK& C, const float4* ms4p, u64* e2)
{
    u64 ps[4];
#pragma unroll
    for (int j = 0; j < KPL / 2; j++) {
        uint32_t ba = tf_fold(A.x, A.y, A.z, A.w, B.x, B.y, B.z, B.w,
                              cb + 32u * (uint32_t)(2 * j), one);
        uint32_t bb = tf_fold(A.x, A.y, A.z, A.w, B.x, B.y, B.z, B.w,
                              cb + 32u * (uint32_t)(2 * j + 1), one);
        // ONE I2F per element of the full word; u = bits*2^-31 + LO.
        // (Rounds vs XLA's truncation: <=2^-24 perturbation; u stays in
        //  [LO, 1-2^-24] -- never -1, so lg2 input > 0 always.)
        float mfa = (float)ba;
        float mfb = (float)bb;
        u64 mf2 = pack2(mfa, mfb);
        u64 u2 = fma2(mf2, C.SCL, C.CLO);
        u64 nu2 = mul2(u2, C.CM1);
        u64 t2 = fma2(nu2, u2, C.C1);        // 1 - u^2 > 0
        float ta, tb;
        unpack2(t2, ta, tb);
        float lga, lgb;
        asm("lg2.approx.f32 %0, %1;" : "=f"(lga) : "f"(ta));
        asm("lg2.approx.f32 %0, %1;" : "=f"(lgb) : "f"(tb));
        u64 lgp = pack2(lga, lgb);
        u64 ww2 = fma2(lgp, C.CNL2, C.CN25); // w - 2.5
        u64 p2 = C.P6;
        p2 = fma2(p2, ww2, C.P5);
        p2 = fma2(p2, ww2, C.P4);
        p2 = fma2(p2, ww2, C.P3);
        p2 = fma2(p2, ww2, C.P2c);
        p2 = fma2(p2, ww2, C.P1);
        p2 = fma2(p2, ww2, C.P0);
        if (__builtin_expect(!!(lga <= C.TH), 0)) {
            float pa, pb;
            unpack2(p2, pa, pb);
            p2 = pack2(erfinv_tail_p(lga), pb);
        }
        if (__builtin_expect(!!(lgb <= C.TH), 0)) {
            float pa, pb;
            unpack2(p2, pa, pb);
            p2 = pack2(pa, erfinv_tail_p(lgb));
        }
        u64 g2 = mul2(p2, u2);               // erfinv(u) pair
        float4 msk = ms4p[j * NTHREADS];
        u64 m2p = pack2(msk.x, msk.y);
        u64 s3p = pack2(msk.z, msk.w);
        u64 tt2 = fma2(g2, s3p, m2p);        // (mean+eps)*log2e pair
        float ca, cbv;
        unpack2(tt2, ca, cbv);
        float eva, evb;
        asm("ex2.approx.f32 %0, %1;" : "=f"(eva) : "f"(ca));
        asm("ex2.approx.f32 %0, %1;" : "=f"(evb) : "f"(cbv));
        u64 ev2 = pack2(eva, evb);
        e2[j] = ev2;
        if (j & 1) ps[j >> 1] = add2(e2[j - 1], ev2);  // pairwise level 0
    }
    // tree levels 1..2 (packed), then horizontal.
    u64 q0 = add2(ps[0], ps[1]);
    u64 q1 = add2(ps[2], ps[3]);
    u64 q = add2(q0, q1);
    float pa, pb;
    unpack2(q, pa, pb);
    return pa + pb;
}

__global__ void __launch_bounds__(NTHREADS, 3)
mc_softmax_kernel(const float* __restrict__ mean,
                  const float* __restrict__ var,
                  const int* __restrict__ d_ns,
                  float* __restrict__ out,
                  uint32_t one) {
    __shared__ float4 ms4[(KPL / 2) * NTHREADS];  // 32 KB (m2 pair, s3 pair)
    __shared__ uint4 skA[MAX_SAMPLES];            // (k0,k1,k2,i1)
    __shared__ uint4 skB[MAX_SAMPLES];            // (i2,i3,i4,i5)

    int ns = d_ns ? *d_ns : 400;
    if (ns > MAX_SAMPLES) ns = MAX_SAMPLES;

    int tid = threadIdx.x;
    for (int s = tid; s < ns; s += NTHREADS) {
        uint2 key = threefry2x32_c(0u, 42u, 0u, (uint32_t)s);
        uint32_t k0 = key.x, k1 = key.y;
        uint32_t k2 = k0 ^ k1 ^ 0x1BD11BDAu;
        skA[s] = make_uint4(k0, k1, k2, k2 + 1u);
        skB[s] = make_uint4(k0 + 2u, k1 + 3u, k2 + 4u, k0 + 5u);
    }

    int warp = tid >> 5;
    int lane = tid & 31;
    int row = blockIdx.x * WARPS_PER_BLOCK + warp;
    int base = row * NCOLS + lane;

    const float LOG2E = 1.4426950408889634f;
    const float S2LOG2E = 1.41421356237309504880f * 1.4426950408889634f;

    u64 acc2[KPL / 2];
#pragma unroll
    for (int j = 0; j < KPL / 2; j++) {
        int ia = base + 32 * (2 * j);
        int ib = base + 32 * (2 * j + 1);
        float4 v;
        v.x = mean[ia] * LOG2E;
        v.y = mean[ib] * LOG2E;
        v.z = sqrtf(var[ia]) * S2LOG2E;
        v.w = sqrtf(var[ib]) * S2LOG2E;
        ms4[j * NTHREADS + tid] = v;
        acc2[j] = pack2(0.0f, 0.0f);
    }
    __syncthreads();

    const float LOs = __int_as_float(0xBF7FFFFF);  // nextafter(-1, 0)
    PK C;
    C.SCL  = pack2(0x1p-31f, 0x1p-31f);
    C.CLO  = pack2(LOs, LOs);
    C.CM1  = pack2(-1.0f, -1.0f);
    C.C1   = pack2(1.0f, 1.0f);
    C.CNL2 = pack2(-0.6931471805599453f, -0.6931471805599453f);
    C.CN25 = pack2(-2.5f, -2.5f);
    C.P6   = pack2(-3.5233877e-06f, -3.5233877e-06f);
    C.P5   = pack2(-4.39150654e-06f, -4.39150654e-06f);
    C.P4   = pack2(0.00021858087f, 0.00021858087f);
    C.P3   = pack2(-0.00125372503f, -0.00125372503f);
    C.P2c  = pack2(-0.00417768164f, -0.00417768164f);
    C.P1   = pack2(0.246640727f, 0.246640727f);
    C.P0   = pack2(1.50140941f, 1.50140941f);
    C.TH   = -7.2134752044448170f;

    const float4* ms4p = ms4 + tid;

    // Staggered sample order (sum is order-independent).
    int s0 = ((blockIdx.x * WARPS_PER_BLOCK + warp) * 13) % ns;

    int idx = s0;
    for (int s = 0; s < ns; s += 2) {
        // ---- sample s ----
        {
            uint4 A = skA[idx];
            uint4 B = skB[idx];
            if (++idx == ns) idx = 0;
            uint32_t cb = (uint32_t)base + A.y;
            u64 e2[KPL / 2];
            float part = sample_eval(A, B, cb, one, C, ms4p, e2);
#pragma unroll
            for (int o = 16; o > 0; o >>= 1)
                part += __shfl_xor_sync(0xffffffffu, part, o);
            float rinv;
            asm("rcp.approx.f32 %0, %1;" : "=f"(rinv) : "f"(part));
            u64 rinv2 = pack2(rinv, rinv);
#pragma unroll
            for (int j = 0; j < KPL / 2; j++)
                acc2[j] = fma2(e2[j], rinv2, acc2[j]);
        }
        // ---- sample s+1 (ns=400 is even; guard for generality) ----
        if (s + 1 < ns) {
            uint4 A = skA[idx];
            uint4 B = skB[idx];
            if (++idx == ns) idx = 0;
            uint32_t cb = (uint32_t)base + A.y;
            u64 e2[KPL / 2];
            float part = sample_eval(A, B, cb, one, C, ms4p, e2);
#pragma unroll
            for (int o = 16; o > 0; o >>= 1)
                part += __shfl_xor_sync(0xffffffffu, part, o);
            float rinv;
            asm("rcp.approx.f32 %0, %1;" : "=f"(rinv) : "f"(part));
            u64 rinv2 = pack2(rinv, rinv);
#pragma unroll
            for (int j = 0; j < KPL / 2; j++)
                acc2[j] = fma2(e2[j], rinv2, acc2[j]);
        }
    }

    float inv = 1.0f / (float)ns;
#pragma unroll
    for (int j = 0; j < KPL / 2; j++) {
        float aa, ab;
        unpack2(acc2[j], aa, ab);
        out[base + 32 * (2 * j)] = aa * inv;
        out[base + 32 * (2 * j + 1)] = ab * inv;
    }
}

extern "C" void kernel_launch(void* const* d_in, const int* in_sizes, int n_in,
                              void* d_out, int out_size) {
    const float* mean = (const float*)d_in[0];
    const float* var = (const float*)d_in[1];
    const int* ns = (n_in >= 3) ? (const int*)d_in[2] : nullptr;
    float* out = (float*)d_out;

    dim3 grid(NROWS / WARPS_PER_BLOCK);
    dim3 block(NTHREADS);
    mc_softmax_kernel<<<grid, block>>>(mean, var, ns, out, 1u);
}

// round 14
// speedup vs baseline: 1.0880x; 1.0880x over previous
#include <cuda_runtime.h>
#include <cstdint>

// ============================================================================
// Monte-Carlo E[softmax(mean + eps)], JAX threefry-partitionable bit-exact RNG.
// R14 = R12 (best: packed FFMA2, umulhi-truncate uniform path) + pure
// latency/reassociation tweaks (slot-neutral):
//   * pairwise tree part-sum (dep chain 32 -> 12 cyc);
//   * nu = -u computed independently (RN sign-symmetric => exact);
//   * u*s3 computed early, folded as p*(u*s3)+m2 (post-poly chain -4 cyc).
// R13's full-word I2F reverted: truncation is load-bearing (erfinv tail
// derivative ~3.5e6 amplifies 2^-24 u-perturbations to 2.6e-4 rel_err).
// ============================================================================

#define NROWS 16384
#define NCOLS 512
#define WARPS_PER_BLOCK 8
#define NTHREADS (WARPS_PER_BLOCK * 32)
#define KPL 16
#define MAX_SAMPLES 512

typedef unsigned long long u64;

// ---- packed f32x2 helpers ----
__device__ __forceinline__ u64 pack2(float lo, float hi) {
    u64 r;
    asm("mov.b64 %0, {%1, %2};" : "=l"(r) : "f"(lo), "f"(hi));
    return r;
}
__device__ __forceinline__ void unpack2(u64 v, float& lo, float& hi) {
    asm("mov.b64 {%0, %1}, %2;" : "=f"(lo), "=f"(hi) : "l"(v));
}
__device__ __forceinline__ u64 fma2(u64 a, u64 b, u64 c) {
    u64 r;
    asm("fma.rn.f32x2 %0, %1, %2, %3;" : "=l"(r) : "l"(a), "l"(b), "l"(c));
    return r;
}
__device__ __forceinline__ u64 mul2(u64 a, u64 b) {
    u64 r;
    asm("mul.rn.f32x2 %0, %1, %2;" : "=l"(r) : "l"(a), "l"(b));
    return r;
}
__device__ __forceinline__ u64 add2(u64 a, u64 b) {
    u64 r;
    asm("add.rn.f32x2 %0, %1, %2;" : "=l"(r) : "l"(a), "l"(b));
    return r;
}

// a + b on the integer-MAD pipe: a*one + b, `one` opaque to ptxas.
__device__ __forceinline__ uint32_t madd(uint32_t a, uint32_t b, uint32_t one) {
    uint32_t t;
    asm("mad.lo.u32 %0, %1, %2, %3;" : "=r"(t) : "r"(a), "r"(one), "r"(b));
    return t;
}
__device__ __forceinline__ uint32_t rots(uint32_t x1, int r, uint32_t x0) {
    return __funnelshift_l(x1, x1, r) ^ x0;
}

// Compile-time threefry for per-sample subkeys (amortized, per block).
__device__ __forceinline__ void tf_round_c(uint32_t& x0, uint32_t& x1, int r) {
    x0 += x1;
    x1 = __funnelshift_l(x1, x1, r);
    x1 ^= x0;
}
__device__ __forceinline__ uint2 threefry2x32_c(uint32_t k0, uint32_t k1,
                                                uint32_t c0, uint32_t c1) {
    uint32_t k2 = k0 ^ k1 ^ 0x1BD11BDAu;
    uint32_t x0 = c0 + k0;
    uint32_t x1 = c1 + k1;
    tf_round_c(x0,x1,13); tf_round_c(x0,x1,15); tf_round_c(x0,x1,26); tf_round_c(x0,x1,6);
    x0 += k1; x1 += k2 + 1u;
    tf_round_c(x0,x1,17); tf_round_c(x0,x1,29); tf_round_c(x0,x1,16); tf_round_c(x0,x1,24);
    x0 += k2; x1 += k0 + 2u;
    tf_round_c(x0,x1,13); tf_round_c(x0,x1,15); tf_round_c(x0,x1,26); tf_round_c(x0,x1,6);
    x0 += k0; x1 += k1 + 3u;
    tf_round_c(x0,x1,17); tf_round_c(x0,x1,29); tf_round_c(x0,x1,16); tf_round_c(x0,x1,24);
    x0 += k1; x1 += k2 + 4u;
    tf_round_c(x0,x1,13); tf_round_c(x0,x1,15); tf_round_c(x0,x1,26); tf_round_c(x0,x1,6);
    x0 += k2; x1 += k0 + 5u;
    return make_uint2(x0, x1);
}

// Hot fold (R6 form): counter (0, c1), x1 pre-added (c1 + k1). Returns x0^x1.
__device__ __forceinline__ uint32_t tf_fold(
    uint32_t k0, uint32_t k1, uint32_t k2,
    uint32_t i1, uint32_t i2, uint32_t i3, uint32_t i4, uint32_t i5,
    uint32_t x1, uint32_t one)
{
    uint32_t x0;
    x0 = madd(x1, k0, one);          x1 = rots(x1, 13, x0);
    x0 = madd(x1, x0, one);          x1 = rots(x1, 15, x0);
    x0 = madd(x1, x0, one);          x1 = rots(x1, 26, x0);
    x0 = madd(x1, x0, one);          x1 = rots(x1,  6, x0);
    x1 = madd(i1, x1, one);
    x0 = x0 + k1 + x1;               x1 = rots(x1, 17, x0);
    x0 = madd(x1, x0, one);          x1 = rots(x1, 29, x0);
    x0 = madd(x1, x0, one);          x1 = rots(x1, 16, x0);
    x0 = madd(x1, x0, one);          x1 = rots(x1, 24, x0);
    x1 = madd(i2, x1, one);
    x0 = x0 + k2 + x1;               x1 = rots(x1, 13, x0);
    x0 = madd(x1, x0, one);          x1 = rots(x1, 15, x0);
    x0 = madd(x1, x0, one);          x1 = rots(x1, 26, x0);
    x0 = madd(x1, x0, one);          x1 = rots(x1,  6, x0);
    x1 = madd(i3, x1, one);
    x0 = x0 + k0 + x1;               x1 = rots(x1, 17, x0);
    x0 = madd(x1, x0, one);          x1 = rots(x1, 29, x0);
    x0 = madd(x1, x0, one);          x1 = rots(x1, 16, x0);
    x0 = madd(x1, x0, one);          x1 = rots(x1, 24, x0);
    x1 = madd(i4, x1, one);
    x0 = x0 + k1 + x1;               x1 = rots(x1, 13, x0);
    x0 = madd(x1, x0, one);          x1 = rots(x1, 15, x0);
    x0 = madd(x1, x0, one);          x1 = rots(x1, 26, x0);
    x0 = madd(x1, x0, one);          x1 = rots(x1,  6, x0);
    return (x0 + k2) ^ madd(i5, x1, one);
}

// Scalar XLA ErfInv p (rare tail patch-up; P ~ 0.34% per half).
__device__ __noinline__ float erfinv_tail_p(float lg) {
    float w = lg * -0.6931471805599453f;
    float sw;
    asm("sqrt.approx.f32 %0, %1;" : "=f"(sw) : "f"(w));
    float v = sw - 3.0f;
    float p = -0.000200214257f;
    p = fmaf(p, v, 0.000100950558f);
    p = fmaf(p, v, 0.00134934322f);
    p = fmaf(p, v, -0.00367342844f);
    p = fmaf(p, v, 0.00573950773f);
    p = fmaf(p, v, -0.0076224613f);
    p = fmaf(p, v, 0.00943887047f);
    p = fmaf(p, v, 1.00167406f);
    p = fmaf(p, v, 2.83297682f);
    return p;
}

__global__ void __launch_bounds__(NTHREADS, 3)
mc_softmax_kernel(const float* __restrict__ mean,
                  const float* __restrict__ var,
                  const int* __restrict__ d_ns,
                  float* __restrict__ out,
                  uint32_t one) {
    __shared__ float4 ms4[(KPL / 2) * NTHREADS];  // 32 KB (m2 pair, s3 pair)
    __shared__ uint4 skA[MAX_SAMPLES];            // (k0,k1,k2,i1)
    __shared__ uint4 skB[MAX_SAMPLES];            // (i2,i3,i4,i5)

    int ns = d_ns ? *d_ns : 400;
    if (ns > MAX_SAMPLES) ns = MAX_SAMPLES;

    int tid = threadIdx.x;
    for (int s = tid; s < ns; s += NTHREADS) {
        uint2 key = threefry2x32_c(0u, 42u, 0u, (uint32_t)s);
        uint32_t k0 = key.x, k1 = key.y;
        uint32_t k2 = k0 ^ k1 ^ 0x1BD11BDAu;
        skA[s] = make_uint4(k0, k1, k2, k2 + 1u);
        skB[s] = make_uint4(k0 + 2u, k1 + 3u, k2 + 4u, k0 + 5u);
    }

    int warp = tid >> 5;
    int lane = tid & 31;
    int row = blockIdx.x * WARPS_PER_BLOCK + warp;
    int base = row * NCOLS + lane;

    const float LOG2E = 1.4426950408889634f;
    const float S2LOG2E = 1.41421356237309504880f * 1.4426950408889634f;

    u64 acc2[KPL / 2];
#pragma unroll
    for (int j = 0; j < KPL / 2; j++) {
        int ia = base + 32 * (2 * j);
        int ib = base + 32 * (2 * j + 1);
        float4 v;
        v.x = mean[ia] * LOG2E;
        v.y = mean[ib] * LOG2E;
        v.z = sqrtf(var[ia]) * S2LOG2E;
        v.w = sqrtf(var[ib]) * S2LOG2E;
        ms4[j * NTHREADS + tid] = v;
        acc2[j] = pack2(0.0f, 0.0f);
    }
    __syncthreads();

    const float LOs = __int_as_float(0xBF7FFFFF);  // nextafter(-1, 0)
    // Packed constants (warp-uniform).
    const u64 SCL   = pack2(0x1p-22f, 0x1p-22f);
    const u64 NSCL  = pack2(-0x1p-22f, -0x1p-22f);
    const u64 CLO   = pack2(LOs, LOs);
    const u64 NCLO  = pack2(-LOs, -LOs);
    const u64 C1    = pack2(1.0f, 1.0f);
    const u64 CNL2  = pack2(-0.6931471805599453f, -0.6931471805599453f);
    const u64 CN25  = pack2(-2.5f, -2.5f);
    const u64 P6    = pack2(-3.5233877e-06f, -3.5233877e-06f);
    const u64 P5    = pack2(-4.39150654e-06f, -4.39150654e-06f);
    const u64 P4    = pack2(0.00021858087f, 0.00021858087f);
    const u64 P3    = pack2(-0.00125372503f, -0.00125372503f);
    const u64 P2c   = pack2(-0.00417768164f, -0.00417768164f);
    const u64 P1    = pack2(0.246640727f, 0.246640727f);
    const u64 P0    = pack2(1.50140941f, 1.50140941f);
    const float TH = -7.2134752044448170f;  // lg threshold for w >= 5

    // Staggered sample order (sum is order-independent).
    int s0 = ((blockIdx.x * WARPS_PER_BLOCK + warp) * 13) % ns;

    int idx = s0;
    for (int s = 0; s < ns; s++) {
        uint4 A = skA[idx];   // k0,k1,k2,i1
        uint4 B = skB[idx];   // i2,i3,i4,i5
        if (++idx == ns) idx = 0;
        uint32_t cb = (uint32_t)base + A.y;  // x1_init = counter + k1

        u64 e2[KPL / 2];
        u64 ps[KPL / 4];
#pragma unroll
        for (int j = 0; j < KPL / 2; j++) {
            uint32_t ba = tf_fold(A.x, A.y, A.z, A.w, B.x, B.y, B.z, B.w,
                                  cb + 32u * (uint32_t)(2 * j), one);
            uint32_t bb = tf_fold(A.x, A.y, A.z, A.w, B.x, B.y, B.z, B.w,
                                  cb + 32u * (uint32_t)(2 * j + 1), one);
            // PROVEN uniform path (packed): mf = I2F(bits>>9) via umulhi
            // (TRUNCATION — load-bearing for tail accuracy),
            // u = mf * 2^-22 + LO  (u in [LO, 1-2^-23], never -1).
            float mfa = (float)__umulhi(ba, 0x00800000u);
            float mfb = (float)__umulhi(bb, 0x00800000u);
            u64 mf2 = pack2(mfa, mfb);
            u64 u2 = fma2(mf2, SCL, CLO);
            // -u computed independently (RN sign-symmetric => exactly -u).
            u64 nu2 = fma2(mf2, NSCL, NCLO);
            u64 t2 = fma2(nu2, u2, C1);        // 1 - u^2 > 0
            // u*s3 early — overlaps the poly; g never materialized.
            float4 msk = ms4[j * NTHREADS + tid];
            u64 s3p = pack2(msk.z, msk.w);
            u64 us3 = mul2(u2, s3p);
            float ta, tb;
            unpack2(t2, ta, tb);
            float lga, lgb;
            asm("lg2.approx.f32 %0, %1;" : "=f"(lga) : "f"(ta));
            asm("lg2.approx.f32 %0, %1;" : "=f"(lgb) : "f"(tb));
            u64 lgp = pack2(lga, lgb);
            u64 ww2 = fma2(lgp, CNL2, CN25);   // w - 2.5
            u64 p2 = P6;
            p2 = fma2(p2, ww2, P5);
            p2 = fma2(p2, ww2, P4);
            p2 = fma2(p2, ww2, P3);
            p2 = fma2(p2, ww2, P2c);
            p2 = fma2(p2, ww2, P1);
            p2 = fma2(p2, ww2, P0);
            // rare tails: patch halves scalar.
            if (__builtin_expect(!!(lga <= TH), 0)) {
                float pa, pb;
                unpack2(p2, pa, pb);
                p2 = pack2(erfinv_tail_p(lga), pb);
            }
            if (__builtin_expect(!!(lgb <= TH), 0)) {
                float pa, pb;
                unpack2(p2, pa, pb);
                p2 = pack2(pa, erfinv_tail_p(lgb));
            }
            u64 m2p = pack2(msk.x, msk.y);
            u64 tt2 = fma2(p2, us3, m2p);      // p*(u*s3) + m2
            float ca, cbv;
            unpack2(tt2, ca, cbv);
            float eva, evb;
            asm("ex2.approx.f32 %0, %1;" : "=f"(eva) : "f"(ca));
            asm("ex2.approx.f32 %0, %1;" : "=f"(evb) : "f"(cbv));
            u64 ev2 = pack2(eva, evb);
            e2[j] = ev2;
            if (j & 1) ps[j >> 1] = add2(e2[j - 1], ev2);  // pairwise L0
        }
        // packed tree levels, then horizontal.
        u64 q0 = add2(ps[0], ps[1]);
        u64 q1 = add2(ps[2], ps[3]);
        u64 q = add2(q0, q1);
        float pa, pb;
        unpack2(q, pa, pb);
        float part = pa + pb;
#pragma unroll
        for (int o = 16; o > 0; o >>= 1)
            part += __shfl_xor_sync(0xffffffffu, part, o);
        float rinv;
        asm("rcp.approx.f32 %0, %1;" : "=f"(rinv) : "f"(part));
        u64 rinv2 = pack2(rinv, rinv);
#pragma unroll
        for (int j = 0; j < KPL / 2; j++)
            acc2[j] = fma2(e2[j], rinv2, acc2[j]);
    }

    float inv = 1.0f / (float)ns;
#pragma unroll
    for (int j = 0; j < KPL / 2; j++) {
        float aa, ab;
        unpack2(acc2[j], aa, ab);
        out[base + 32 * (2 * j)] = aa * inv;
        out[base + 32 * (2 * j + 1)] = ab * inv;
    }
}

extern "C" void kernel_launch(void* const* d_in, const int* in_sizes, int n_in,
                              void* d_out, int out_size) {
    const float* mean = (const float*)d_in[0];
    const float* var = (const float*)d_in[1];
    const int* ns = (n_in >= 3) ? (const int*)d_in[2] : nullptr;
    float* out = (float*)d_out;

    dim3 grid(NROWS / WARPS_PER_BLOCK);
    dim3 block(NTHREADS);
    mc_softmax_kernel<<<grid, block>>>(mean, var, ns, out, 1u);
}

// round 15
// speedup vs baseline: 1.1054x; 1.0160x over previous
#include <cuda_runtime.h>
#include <cstdint>

// ============================================================================
// Monte-Carlo E[softmax(mean + eps)], JAX threefry-partitionable bit-exact RNG.
// R15 = R12 (best) with cheaper tail handling:
//   * ONE combined rare-branch per element pair (fmin(lga,lgb) <= TH) instead
//     of two — halves the always-issued FSETP/BSSY/BSYNC cost;
//   * tail polynomial inlined (no CALL/RET front-end flush in the cold arm).
// Arithmetic identical to R12 (rel_err 3.15e-6 expected unchanged).
// ============================================================================

#define NROWS 16384
#define NCOLS 512
#define WARPS_PER_BLOCK 8
#define NTHREADS (WARPS_PER_BLOCK * 32)
#define KPL 16
#define MAX_SAMPLES 512

typedef unsigned long long u64;

// ---- packed f32x2 helpers ----
__device__ __forceinline__ u64 pack2(float lo, float hi) {
    u64 r;
    asm("mov.b64 %0, {%1, %2};" : "=l"(r) : "f"(lo), "f"(hi));
    return r;
}
__device__ __forceinline__ void unpack2(u64 v, float& lo, float& hi) {
    asm("mov.b64 {%0, %1}, %2;" : "=f"(lo), "=f"(hi) : "l"(v));
}
__device__ __forceinline__ u64 fma2(u64 a, u64 b, u64 c) {
    u64 r;
    asm("fma.rn.f32x2 %0, %1, %2, %3;" : "=l"(r) : "l"(a), "l"(b), "l"(c));
    return r;
}
__device__ __forceinline__ u64 mul2(u64 a, u64 b) {
    u64 r;
    asm("mul.rn.f32x2 %0, %1, %2;" : "=l"(r) : "l"(a), "l"(b));
    return r;
}
__device__ __forceinline__ u64 add2(u64 a, u64 b) {
    u64 r;
    asm("add.rn.f32x2 %0, %1, %2;" : "=l"(r) : "l"(a), "l"(b));
    return r;
}

// a + b on the integer-MAD pipe: a*one + b, `one` opaque to ptxas.
__device__ __forceinline__ uint32_t madd(uint32_t a, uint32_t b, uint32_t one) {
    uint32_t t;
    asm("mad.lo.u32 %0, %1, %2, %3;" : "=r"(t) : "r"(a), "r"(one), "r"(b));
    return t;
}
__device__ __forceinline__ uint32_t rots(uint32_t x1, int r, uint32_t x0) {
    return __funnelshift_l(x1, x1, r) ^ x0;
}

// Compile-time threefry for per-sample subkeys (amortized, per block).
__device__ __forceinline__ void tf_round_c(uint32_t& x0, uint32_t& x1, int r) {
    x0 += x1;
    x1 = __funnelshift_l(x1, x1, r);
    x1 ^= x0;
}
__device__ __forceinline__ uint2 threefry2x32_c(uint32_t k0, uint32_t k1,
                                                uint32_t c0, uint32_t c1) {
    uint32_t k2 = k0 ^ k1 ^ 0x1BD11BDAu;
    uint32_t x0 = c0 + k0;
    uint32_t x1 = c1 + k1;
    tf_round_c(x0,x1,13); tf_round_c(x0,x1,15); tf_round_c(x0,x1,26); tf_round_c(x0,x1,6);
    x0 += k1; x1 += k2 + 1u;
    tf_round_c(x0,x1,17); tf_round_c(x0,x1,29); tf_round_c(x0,x1,16); tf_round_c(x0,x1,24);
    x0 += k2; x1 += k0 + 2u;
    tf_round_c(x0,x1,13); tf_round_c(x0,x1,15); tf_round_c(x0,x1,26); tf_round_c(x0,x1,6);
    x0 += k0; x1 += k1 + 3u;
    tf_round_c(x0,x1,17); tf_round_c(x0,x1,29); tf_round_c(x0,x1,16); tf_round_c(x0,x1,24);
    x0 += k1; x1 += k2 + 4u;
    tf_round_c(x0,x1,13); tf_round_c(x0,x1,15); tf_round_c(x0,x1,26); tf_round_c(x0,x1,6);
    x0 += k2; x1 += k0 + 5u;
    return make_uint2(x0, x1);
}

// Hot fold (R6 form): counter (0, c1), x1 pre-added (c1 + k1). Returns x0^x1.
__device__ __forceinline__ uint32_t tf_fold(
    uint32_t k0, uint32_t k1, uint32_t k2,
    uint32_t i1, uint32_t i2, uint32_t i3, uint32_t i4, uint32_t i5,
    uint32_t x1, uint32_t one)
{
    uint32_t x0;
    x0 = madd(x1, k0, one);          x1 = rots(x1, 13, x0);
    x0 = madd(x1, x0, one);          x1 = rots(x1, 15, x0);
    x0 = madd(x1, x0, one);          x1 = rots(x1, 26, x0);
    x0 = madd(x1, x0, one);          x1 = rots(x1,  6, x0);
    x1 = madd(i1, x1, one);
    x0 = x0 + k1 + x1;               x1 = rots(x1, 17, x0);
    x0 = madd(x1, x0, one);          x1 = rots(x1, 29, x0);
    x0 = madd(x1, x0, one);          x1 = rots(x1, 16, x0);
    x0 = madd(x1, x0, one);          x1 = rots(x1, 24, x0);
    x1 = madd(i2, x1, one);
    x0 = x0 + k2 + x1;               x1 = rots(x1, 13, x0);
    x0 = madd(x1, x0, one);          x1 = rots(x1, 15, x0);
    x0 = madd(x1, x0, one);          x1 = rots(x1, 26, x0);
    x0 = madd(x1, x0, one);          x1 = rots(x1,  6, x0);
    x1 = madd(i3, x1, one);
    x0 = x0 + k0 + x1;               x1 = rots(x1, 17, x0);
    x0 = madd(x1, x0, one);          x1 = rots(x1, 29, x0);
    x0 = madd(x1, x0, one);          x1 = rots(x1, 16, x0);
    x0 = madd(x1, x0, one);          x1 = rots(x1, 24, x0);
    x1 = madd(i4, x1, one);
    x0 = x0 + k1 + x1;               x1 = rots(x1, 13, x0);
    x0 = madd(x1, x0, one);          x1 = rots(x1, 15, x0);
    x0 = madd(x1, x0, one);          x1 = rots(x1, 26, x0);
    x0 = madd(x1, x0, one);          x1 = rots(x1,  6, x0);
    return (x0 + k2) ^ madd(i5, x1, one);
}

// Scalar XLA ErfInv tail p (INLINE — lives only inside the rare cold arm).
__device__ __forceinline__ float erfinv_tail_p(float lg) {
    float w = lg * -0.6931471805599453f;
    float sw;
    asm("sqrt.approx.f32 %0, %1;" : "=f"(sw) : "f"(w));
    float v = sw - 3.0f;
    float p = -0.000200214257f;
    p = fmaf(p, v, 0.000100950558f);
    p = fmaf(p, v, 0.00134934322f);
    p = fmaf(p, v, -0.00367342844f);
    p = fmaf(p, v, 0.00573950773f);
    p = fmaf(p, v, -0.0076224613f);
    p = fmaf(p, v, 0.00943887047f);
    p = fmaf(p, v, 1.00167406f);
    p = fmaf(p, v, 2.83297682f);
    return p;
}

__global__ void __launch_bounds__(NTHREADS, 3)
mc_softmax_kernel(const float* __restrict__ mean,
                  const float* __restrict__ var,
                  const int* __restrict__ d_ns,
                  float* __restrict__ out,
                  uint32_t one) {
    __shared__ float4 ms4[(KPL / 2) * NTHREADS];  // 32 KB (m2 pair, s3 pair)
    __shared__ uint4 skA[MAX_SAMPLES];            // (k0,k1,k2,i1)
    __shared__ uint4 skB[MAX_SAMPLES];            // (i2,i3,i4,i5)

    int ns = d_ns ? *d_ns : 400;
    if (ns > MAX_SAMPLES) ns = MAX_SAMPLES;

    int tid = threadIdx.x;
    for (int s = tid; s < ns; s += NTHREADS) {
        uint2 key = threefry2x32_c(0u, 42u, 0u, (uint32_t)s);
        uint32_t k0 = key.x, k1 = key.y;
        uint32_t k2 = k0 ^ k1 ^ 0x1BD11BDAu;
        skA[s] = make_uint4(k0, k1, k2, k2 + 1u);
        skB[s] = make_uint4(k0 + 2u, k1 + 3u, k2 + 4u, k0 + 5u);
    }

    int warp = tid >> 5;
    int lane = tid & 31;
    int row = blockIdx.x * WARPS_PER_BLOCK + warp;
    int base = row * NCOLS + lane;

    const float LOG2E = 1.4426950408889634f;
    const float S2LOG2E = 1.41421356237309504880f * 1.4426950408889634f;

    u64 acc2[KPL / 2];
#pragma unroll
    for (int j = 0; j < KPL / 2; j++) {
        int ia = base + 32 * (2 * j);
        int ib = base + 32 * (2 * j + 1);
        float4 v;
        v.x = mean[ia] * LOG2E;
        v.y = mean[ib] * LOG2E;
        v.z = sqrtf(var[ia]) * S2LOG2E;
        v.w = sqrtf(var[ib]) * S2LOG2E;
        ms4[j * NTHREADS + tid] = v;
        acc2[j] = pack2(0.0f, 0.0f);
    }
    __syncthreads();

    const float LOs = __int_as_float(0xBF7FFFFF);  // nextafter(-1, 0)
    // Packed constants (warp-uniform).
    const u64 SCL   = pack2(0x1p-22f, 0x1p-22f);
    const u64 CLO   = pack2(LOs, LOs);
    const u64 CM1   = pack2(-1.0f, -1.0f);
    const u64 C1    = pack2(1.0f, 1.0f);
    const u64 CNL2  = pack2(-0.6931471805599453f, -0.6931471805599453f);
    const u64 CN25  = pack2(-2.5f, -2.5f);
    const u64 P6    = pack2(-3.5233877e-06f, -3.5233877e-06f);
    const u64 P5    = pack2(-4.39150654e-06f, -4.39150654e-06f);
    const u64 P4    = pack2(0.00021858087f, 0.00021858087f);
    const u64 P3    = pack2(-0.00125372503f, -0.00125372503f);
    const u64 P2c   = pack2(-0.00417768164f, -0.00417768164f);
    const u64 P1    = pack2(0.246640727f, 0.246640727f);
    const u64 P0    = pack2(1.50140941f, 1.50140941f);
    const float TH = -7.2134752044448170f;  // lg threshold for w >= 5

    // Staggered sample order (sum is order-independent).
    int s0 = ((blockIdx.x * WARPS_PER_BLOCK + warp) * 13) % ns;

    int idx = s0;
    for (int s = 0; s < ns; s++) {
        uint4 A = skA[idx];   // k0,k1,k2,i1
        uint4 B = skB[idx];   // i2,i3,i4,i5
        if (++idx == ns) idx = 0;
        uint32_t cb = (uint32_t)base + A.y;  // x1_init = counter + k1

        u64 e2[KPL / 2];
        u64 part2 = pack2(0.0f, 0.0f);
#pragma unroll
        for (int j = 0; j < KPL / 2; j++) {
            uint32_t ba = tf_fold(A.x, A.y, A.z, A.w, B.x, B.y, B.z, B.w,
                                  cb + 32u * (uint32_t)(2 * j), one);
            uint32_t bb = tf_fold(A.x, A.y, A.z, A.w, B.x, B.y, B.z, B.w,
                                  cb + 32u * (uint32_t)(2 * j + 1), one);
            // PROVEN uniform path (packed): mf = I2F(bits>>9) via umulhi
            // (truncation — load-bearing), u = mf * 2^-22 + LO.
            float mfa = (float)__umulhi(ba, 0x00800000u);
            float mfb = (float)__umulhi(bb, 0x00800000u);
            u64 mf2 = pack2(mfa, mfb);
            u64 u2 = fma2(mf2, SCL, CLO);
            u64 nu2 = mul2(u2, CM1);
            u64 t2 = fma2(nu2, u2, C1);        // 1 - u^2 > 0
            float ta, tb;
            unpack2(t2, ta, tb);
            float lga, lgb;
            asm("lg2.approx.f32 %0, %1;" : "=f"(lga) : "f"(ta));
            asm("lg2.approx.f32 %0, %1;" : "=f"(lgb) : "f"(tb));
            u64 lgp = pack2(lga, lgb);
            u64 ww2 = fma2(lgp, CNL2, CN25);   // w - 2.5
            u64 p2 = P6;
            p2 = fma2(p2, ww2, P5);
            p2 = fma2(p2, ww2, P4);
            p2 = fma2(p2, ww2, P3);
            p2 = fma2(p2, ww2, P2c);
            p2 = fma2(p2, ww2, P1);
            p2 = fma2(p2, ww2, P0);
            // ONE combined rare check per pair; both halves patched inline
            // inside the single cold arm.
            if (__builtin_expect(!!(fminf(lga, lgb) <= TH), 0)) {
                float pa, pb;
                unpack2(p2, pa, pb);
                if (lga <= TH) pa = erfinv_tail_p(lga);
                if (lgb <= TH) pb = erfinv_tail_p(lgb);
                p2 = pack2(pa, pb);
            }
            u64 g2 = mul2(p2, u2);             // erfinv(u) pair
            float4 msk = ms4[j * NTHREADS + tid];
            u64 m2p = pack2(msk.x, msk.y);
            u64 s3p = pack2(msk.z, msk.w);
            u64 tt2 = fma2(g2, s3p, m2p);      // (mean+eps)*log2e pair
            float ca, cbv;
            unpack2(tt2, ca, cbv);
            float eva, evb;
            asm("ex2.approx.f32 %0, %1;" : "=f"(eva) : "f"(ca));
            asm("ex2.approx.f32 %0, %1;" : "=f"(evb) : "f"(cbv));
            u64 ev2 = pack2(eva, evb);
            e2[j] = ev2;
            part2 = add2(part2, ev2);
        }
        float pa, pb;
        unpack2(part2, pa, pb);
        float part = pa + pb;
#pragma unroll
        for (int o = 16; o > 0; o >>= 1)
            part += __shfl_xor_sync(0xffffffffu, part, o);
        float rinv;
        asm("rcp.approx.f32 %0, %1;" : "=f"(rinv) : "f"(part));
        u64 rinv2 = pack2(rinv, rinv);
#pragma unroll
        for (int j = 0; j < KPL / 2; j++)
            acc2[j] = fma2(e2[j], rinv2, acc2[j]);
    }

    float inv = 1.0f / (float)ns;
#pragma unroll
    for (int j = 0; j < KPL / 2; j++) {
        float aa, ab;
        unpack2(acc2[j], aa, ab);
        out[base + 32 * (2 * j)] = aa * inv;
        out[base + 32 * (2 * j + 1)] = ab * inv;
    }
}

extern "C" void kernel_launch(void* const* d_in, const int* in_sizes, int n_in,
                              void* d_out, int out_size) {
    const float* mean = (const float*)d_in[0];
    const float* var = (const float*)d_in[1];
    const int* ns = (n_in >= 3) ? (const int*)d_in[2] : nullptr;
    float* out = (float*)d_out;

    dim3 grid(NROWS / WARPS_PER_BLOCK);
    dim3 block(NTHREADS);
    mc_softmax_kernel<<<grid, block>>>(mean, var, ns, out, 1u);
}